// round 11
// baseline (speedup 1.0000x reference)
#include <cuda_runtime.h>
#include <cuda_bf16.h>
#include <cuda_fp16.h>
#include <cstdint>

#define N_NODES 50000
#define N_EDGES 800000
#define NF      128
#define HID     256
#define HEADS   8
#define CH      32
#define NG      128
#define OUT_DIM 10
#define SLOPE   0.2f

// ---------------- scratch (device globals; no allocation) ----------------
__device__ float   g_h [(size_t)N_NODES * HID];
__device__ float   g_fa[(size_t)N_NODES * HID];
__device__ float   g_fb[(size_t)N_NODES * HID];
__device__ __half2 g_h16[(size_t)N_NODES * (HID / 2)];
__device__ float   g_als[N_NODES * HEADS];
__device__ float   g_ald[N_NODES * HEADS];
__device__ int     g_cnt[N_NODES];
__device__ int     g_rowptr[N_NODES + 1];
__device__ int     g_col[N_EDGES];
__device__ int     g_blk[128];
__device__ int     g_is64_edge;
__device__ int     g_is64_batch;
// B fragments (bf16 hi/lo, mma fragment order): [32 ntile][K/16 ks][32 lane][2 reg]
__device__ uint32_t g_bfrag_hi[32 * 16 * 32 * 2];
__device__ uint32_t g_bfrag_lo[32 * 16 * 32 * 2];

__device__ __forceinline__ float* buf_sel(int s) {
    return (s == 0) ? g_h : (s == 1) ? g_fa : g_fb;
}

__device__ __forceinline__ int ld_idx(const int* __restrict__ w, int i, int is64) {
    return is64 ? w[2 * i] : w[i];
}

// ---------------- dtype detection (int64 vs int32 index tensors) ----------------
__global__ void detect_dtype(const int* __restrict__ ei_w, const int* __restrict__ b_w) {
    int acc = 0;
    for (int i = 0; i < 512; i++) acc |= ei_w[2 * i + 1];
    g_is64_edge = (acc == 0) ? 1 : 0;
    int accb = 0;
    for (int i = N_NODES - 512; i < N_NODES; i += 2) accb |= b_w[i | 1];
    g_is64_batch = (accb == 0) ? 1 : 0;
}

// ---------------- CSR build kernels ----------------
__global__ void zero_cnt() {
    int i = blockIdx.x * blockDim.x + threadIdx.x;
    if (i < N_NODES) g_cnt[i] = 0;
}

__global__ void hist_kernel(const int* __restrict__ ei_w) {
    int e = blockIdx.x * blockDim.x + threadIdx.x;
    int is64 = g_is64_edge;
    if (e < N_EDGES) {
        int d = ld_idx(ei_w, N_EDGES + e, is64);
        atomicAdd(&g_cnt[d], 1);
    }
}

__global__ void scan_block() {
    __shared__ int s[1024];
    int tid = threadIdx.x;
    int i = blockIdx.x * 1024 + tid;
    int v = (i < N_NODES) ? g_cnt[i] : 0;
    s[tid] = v;
    __syncthreads();
    for (int off = 1; off < 1024; off <<= 1) {
        int a = (tid >= off) ? s[tid - off] : 0;
        __syncthreads();
        s[tid] += a;
        __syncthreads();
    }
    if (i < N_NODES) g_rowptr[i] = s[tid] - v;
    if (tid == 1023) g_blk[blockIdx.x] = s[1023];
}

__global__ void scan_top(int n) {
    __shared__ int s[64];
    int tid = threadIdx.x;
    int v = (tid < n) ? g_blk[tid] : 0;
    s[tid] = v;
    __syncthreads();
    for (int off = 1; off < 64; off <<= 1) {
        int a = (tid >= off) ? s[tid - off] : 0;
        __syncthreads();
        s[tid] += a;
        __syncthreads();
    }
    if (tid < n) g_blk[tid] = s[tid] - v;
}

__global__ void scan_add() {
    int i = blockIdx.x * 1024 + threadIdx.x;
    if (i < N_NODES) g_rowptr[i] += g_blk[i >> 10];
    if (i == 0) g_rowptr[N_NODES] = N_EDGES;
}

__global__ void scatter_kernel(const int* __restrict__ ei_w) {
    int e = blockIdx.x * blockDim.x + threadIdx.x;
    int is64 = g_is64_edge;
    if (e < N_EDGES) {
        int d = ld_idx(ei_w, N_EDGES + e, is64);
        int s = ld_idx(ei_w, e, is64);
        int pos = g_rowptr[d] + atomicAdd(&g_cnt[d], 1);
        g_col[pos] = s;
    }
}

// ---------------- bf16 split helpers ----------------
__device__ __forceinline__ void split_pack(float x0, float x1, uint32_t& hp, uint32_t& lp) {
    __nv_bfloat16 h0 = __float2bfloat16(x0);
    __nv_bfloat16 h1 = __float2bfloat16(x1);
    __nv_bfloat16 l0 = __float2bfloat16(x0 - __bfloat162float(h0));
    __nv_bfloat16 l1 = __float2bfloat16(x1 - __bfloat162float(h1));
    hp = ((uint32_t)__bfloat16_as_ushort(h1) << 16) | __bfloat16_as_ushort(h0);
    lp = ((uint32_t)__bfloat16_as_ushort(l1) << 16) | __bfloat16_as_ushort(l0);
}

__device__ __forceinline__ void mma_bf16(float* d, const uint32_t* a, uint32_t b0, uint32_t b1) {
    asm volatile(
        "mma.sync.aligned.m16n8k16.row.col.f32.bf16.bf16.f32 "
        "{%0,%1,%2,%3}, {%4,%5,%6,%7}, {%8,%9}, {%0,%1,%2,%3};"
        : "+f"(d[0]), "+f"(d[1]), "+f"(d[2]), "+f"(d[3])
        : "r"(a[0]), "r"(a[1]), "r"(a[2]), "r"(a[3]), "r"(b0), "r"(b1));
}

// ---------------- B fragment prep: W[K,256] -> hi/lo fragments ----------------
__global__ void prep_bfrag(const float* __restrict__ W, int K) {
    int idx = blockIdx.x * 256 + threadIdx.x;
    int nks = K >> 4;
    int total = 32 * nks * 32;
    if (idx >= total) return;
    int lane = idx & 31;
    int ks = (idx >> 5) % nks;
    int ntile = (idx >> 5) / nks;
    int n = ntile * 8 + (lane >> 2);
    int kb = ks * 16 + (lane & 3) * 2;
    uint32_t h0, l0, h1, l1;
    split_pack(W[(size_t)kb * 256 + n],       W[(size_t)(kb + 1) * 256 + n], h0, l0);
    split_pack(W[(size_t)(kb + 8) * 256 + n], W[(size_t)(kb + 9) * 256 + n], h1, l1);
    g_bfrag_hi[idx * 2 + 0] = h0;
    g_bfrag_hi[idx * 2 + 1] = h1;
    g_bfrag_lo[idx * 2 + 0] = l0;
    g_bfrag_lo[idx * 2 + 1] = l1;
}

// ---------------- split-bf16 mma.sync GEMM: g_h[M,256] = A[M,K] @ W[K,256] ----------------
__global__ __launch_bounds__(256) void gemm_mma(const float* __restrict__ Aext,
                                                int a_sel, int K) {
    __shared__ uint32_t sAhi[8 * 4 * 32 * 4];   // 16KB
    __shared__ uint32_t sAlo[8 * 4 * 32 * 4];   // 16KB

    const float* A = (a_sel < 0) ? Aext : buf_sel(a_sel);
    float* C = g_h;
    const int nks = K >> 4;

    int tid = threadIdx.x;
    int lane = tid & 31, wid = tid >> 5;
    int wm = wid & 3, wn = wid >> 2;
    int grp = lane >> 2, tig = lane & 3;
    int bm = blockIdx.y, bn = blockIdx.x;

    int arow = tid >> 1;
    int akb  = (tid & 1) * 32;
    int grow = bm * 128 + arow;
    bool avalid = (grow < N_NODES);
    int amt = arow >> 4, ar8 = (arow >> 3) & 1, agrp = arow & 7;

    float acc[2][8][4];
#pragma unroll
    for (int mt = 0; mt < 2; mt++)
#pragma unroll
        for (int nt = 0; nt < 8; nt++)
#pragma unroll
            for (int r = 0; r < 4; r++) acc[mt][nt][r] = 0.0f;

    const int niter = K >> 6;
    float4 av[8];
    // preload iter 0
#pragma unroll
    for (int jj = 0; jj < 8; jj++)
        av[jj] = avalid ? *(const float4*)(A + (size_t)grow * K + akb + jj * 4)
                        : make_float4(0.f, 0.f, 0.f, 0.f);

    for (int it = 0; it < niter; it++) {
        // ---- convert current registers -> smem fragment order ----
#pragma unroll
        for (int jj = 0; jj < 8; jj++) {
            float4 v = av[jj];
#pragma unroll
            for (int q = 0; q < 2; q++) {
                uint32_t hp, lp;
                split_pack(q ? v.z : v.x, q ? v.w : v.y, hp, lp);
                int kq = akb + jj * 4 + 2 * q;
                int ks = kq >> 4;
                int kk = kq & 15;
                int reg = (kk >> 3) * 2 + ar8;
                int lt = agrp * 4 + ((kk & 7) >> 1);
                int addr = ((amt * 4 + ks) * 32 + lt) * 4 + reg;
                sAhi[addr] = hp;
                sAlo[addr] = lp;
            }
        }
        __syncthreads();

        // ---- prefetch next iter's A while MMAs run ----
        if (it + 1 < niter) {
            const float* Ap = A + (size_t)grow * K + (it + 1) * 64 + akb;
#pragma unroll
            for (int jj = 0; jj < 8; jj++)
                av[jj] = avalid ? *(const float4*)(Ap + jj * 4)
                                : make_float4(0.f, 0.f, 0.f, 0.f);
        }

        // ---- consume: 4 k16-steps ----
#pragma unroll
        for (int ks = 0; ks < 4; ks++) {
            int ksg = it * 4 + ks;
            uint32_t ah[2][4], al[2][4];
#pragma unroll
            for (int mt = 0; mt < 2; mt++) {
                int mtg = wm * 2 + mt;
                int base = ((mtg * 4 + ks) * 32 + lane) * 4;
                *(uint4*)ah[mt] = *(const uint4*)&sAhi[base];
                *(uint4*)al[mt] = *(const uint4*)&sAlo[base];
            }
#pragma unroll
            for (int nt = 0; nt < 8; nt++) {
                int ntg = bn * 16 + wn * 8 + nt;
                int boff = ((ntg * nks + ksg) * 32 + lane);
                uint2 bh = *((const uint2*)g_bfrag_hi + boff);
                uint2 bl = *((const uint2*)g_bfrag_lo + boff);
#pragma unroll
                for (int mt = 0; mt < 2; mt++) {
                    mma_bf16(acc[mt][nt], ah[mt], bl.x, bl.y);
                    mma_bf16(acc[mt][nt], al[mt], bh.x, bh.y);
                    mma_bf16(acc[mt][nt], ah[mt], bh.x, bh.y);
                }
            }
        }
        __syncthreads();
    }

    // ---- epilogue ----
#pragma unroll
    for (int mt = 0; mt < 2; mt++) {
        int r0 = bm * 128 + wm * 32 + mt * 16 + grp;
#pragma unroll
        for (int nt = 0; nt < 8; nt++) {
            int cc = bn * 128 + wn * 64 + nt * 8 + tig * 2;
            if (r0 < N_NODES)
                *(float2*)(C + (size_t)r0 * 256 + cc) = make_float2(acc[mt][nt][0], acc[mt][nt][1]);
            if (r0 + 8 < N_NODES)
                *(float2*)(C + (size_t)(r0 + 8) * 256 + cc) = make_float2(acc[mt][nt][2], acc[mt][nt][3]);
        }
    }
}

// ---------------- attention logits + fp16 pack ----------------
__global__ __launch_bounds__(256) void compute_al(const float* __restrict__ a_src,
                                                  const float* __restrict__ a_dst) {
    int v = blockIdx.x;
    int t = threadIdx.x;
    int w = t >> 5;
    int lane = t & 31;
    float hv = g_h[(size_t)v * HID + t];

    // pack fp16 copy: even thread packs (hv, next thread's hv)
    float partner = __shfl_xor_sync(0xffffffffu, hv, 1);
    if ((t & 1) == 0)
        g_h16[(size_t)v * (HID / 2) + (t >> 1)] = __floats2half2_rn(hv, partner);

    float s1 = hv * a_src[t];
    float s2 = hv * a_dst[t];
#pragma unroll
    for (int off = 16; off; off >>= 1) {
        s1 += __shfl_xor_sync(0xffffffffu, s1, off);
        s2 += __shfl_xor_sync(0xffffffffu, s2, off);
    }
    if (lane == 0) {
        g_als[v * HEADS + w] = s1;
        g_ald[v * HEADS + w] = s2;
    }
}

// ---------------- warp-per-node softmax attention aggregation (fp16 gathers) ----------------
// lane owns channels [lane*8, lane*8+8) -> head = lane>>2 (static). No local-mem arrays.
__global__ __launch_bounds__(256) void gat_aggregate(const float* __restrict__ bias,
                                                     int out_sel) {
    float* out = buf_sel(out_sel);
    int warp = (blockIdx.x * blockDim.x + threadIdx.x) >> 5;
    int lane = threadIdx.x & 31;
    if (warp >= N_NODES) return;
    int v = warp;
    int r0 = g_rowptr[v];
    int deg = g_rowptr[v + 1] - r0;
    int hd = lane >> 2;

    // ---- pass 1: per-head max of als over in-neighbors (+ self) ----
    const float4* als4 = (const float4*)g_als;
    float4 M0 = make_float4(-1e30f, -1e30f, -1e30f, -1e30f);
    float4 M1 = M0;
    for (int i = lane; i < deg + 1; i += 32) {
        int s = (i < deg) ? g_col[r0 + i] : v;
        float4 a0 = als4[s * 2], a1 = als4[s * 2 + 1];
        M0.x = fmaxf(M0.x, a0.x); M0.y = fmaxf(M0.y, a0.y);
        M0.z = fmaxf(M0.z, a0.z); M0.w = fmaxf(M0.w, a0.w);
        M1.x = fmaxf(M1.x, a1.x); M1.y = fmaxf(M1.y, a1.y);
        M1.z = fmaxf(M1.z, a1.z); M1.w = fmaxf(M1.w, a1.w);
    }
    float Mx[8] = {M0.x, M0.y, M0.z, M0.w, M1.x, M1.y, M1.z, M1.w};
#pragma unroll
    for (int k = 0; k < 8; k++)
#pragma unroll
        for (int off = 16; off; off >>= 1)
            Mx[k] = fmaxf(Mx[k], __shfl_xor_sync(0xffffffffu, Mx[k], off));

    float4 ad0 = als4[(N_NODES + v) * 2 - N_NODES * 2 + 0];  // placeholder avoided below
    // load ald directly
    const float4* ald4 = (const float4*)g_ald;
    float4 d0 = ald4[v * 2], d1 = ald4[v * 2 + 1];
    float aldv[8] = {d0.x, d0.y, d0.z, d0.w, d1.x, d1.y, d1.z, d1.w};

    // m per head: leaky(Mx + ald) (leaky_relu is monotonic)
    float mh[8];
#pragma unroll
    for (int k = 0; k < 8; k++) {
        float e = Mx[k] + aldv[k];
        mh[k] = (e > 0.f) ? e : SLOPE * e;
    }
    // ladder-select this lane's head values (static unroll, no local mem)
    float mhd = mh[0], aldhd = aldv[0];
#pragma unroll
    for (int k = 1; k < 8; k++) {
        bool p = (hd == k);
        mhd   = p ? mh[k]   : mhd;
        aldhd = p ? aldv[k] : aldhd;
    }

    // ---- pass 2: fused exp-sum + weighted accumulation ----
    float acc[8];
#pragma unroll
    for (int j = 0; j < 8; j++) acc[j] = 0.0f;
    float den = 0.0f;
    const __half2* h2base = g_h16;
    for (int i = 0; i <= deg; i++) {
        int s = (i < deg) ? g_col[r0 + i] : v;
        float e = g_als[s * HEADS + hd] + aldhd;
        e = (e > 0.f) ? e : SLOPE * e;
        float ex = __expf(e - mhd);
        den += ex;
        const __half2* row = h2base + (size_t)s * (HID / 2) + lane * 4;
#pragma unroll
        for (int j = 0; j < 4; j++) {
            float2 f = __half22float2(row[j]);
            acc[2 * j]     = fmaf(ex, f.x, acc[2 * j]);
            acc[2 * j + 1] = fmaf(ex, f.y, acc[2 * j + 1]);
        }
    }
    float inv = 1.0f / (den + 1e-16f);
    float* op = out + (size_t)v * HID + lane * 8;
    const float* bp = bias + lane * 8;
    float4 o0 = make_float4(acc[0] * inv + bp[0], acc[1] * inv + bp[1],
                            acc[2] * inv + bp[2], acc[3] * inv + bp[3]);
    float4 o1 = make_float4(acc[4] * inv + bp[4], acc[5] * inv + bp[5],
                            acc[6] * inv + bp[6], acc[7] * inv + bp[7]);
    *(float4*)(op + 0) = o0;
    *(float4*)(op + 4) = o1;
}

// ---------------- mean pool (sorted batch) + final linear, fused ----------------
__device__ __forceinline__ int lower_bound_idx(const int* __restrict__ w, int key, int is64) {
    int lo = 0, hi = N_NODES;
    while (lo < hi) {
        int mid = (lo + hi) >> 1;
        if (ld_idx(w, mid, is64) < key) lo = mid + 1; else hi = mid;
    }
    return lo;
}

__global__ __launch_bounds__(256) void pool_linear(const int* __restrict__ batch_w,
                                                   const float* __restrict__ Wl,
                                                   const float* __restrict__ bl,
                                                   float* __restrict__ out,
                                                   int feat_sel) {
    const float* feat = buf_sel(feat_sel);
    int is64 = g_is64_batch;
    int g = blockIdx.x;
    int tid = threadIdx.x;
    int start = lower_bound_idx(batch_w, g, is64);
    int end   = lower_bound_idx(batch_w, g + 1, is64);
    float acc = 0.0f;
    for (int n = start; n < end; n++) acc += feat[(size_t)n * HID + tid];
    int cnt = end - start;
    float pooled = acc / fmaxf((float)cnt, 1.0f);
    __shared__ float spool[HID];
    spool[tid] = pooled;
    __syncthreads();
    if (tid < OUT_DIM) {
        float o = bl[tid];
        for (int c = 0; c < HID; c++) o = fmaf(spool[c], Wl[c * OUT_DIM + tid], o);
        out[g * OUT_DIM + tid] = o;
    }
}

// ---------------- host launch ----------------
extern "C" void kernel_launch(void* const* d_in, const int* in_sizes, int n_in,
                              void* d_out, int out_size) {
    const float* x       = (const float*)d_in[0];
    const int*   ei_w    = (const int*)d_in[1];
    const int*   batch_w = (const int*)d_in[2];
    const float* W0      = (const float*)d_in[3];
    const float* as0     = (const float*)d_in[4];
    const float* ad0     = (const float*)d_in[5];
    const float* b0      = (const float*)d_in[6];
    const float* Wh      = (const float*)d_in[7];
    const float* ash     = (const float*)d_in[8];
    const float* adh     = (const float*)d_in[9];
    const float* bh      = (const float*)d_in[10];
    const float* Wl      = (const float*)d_in[11];
    const float* bl      = (const float*)d_in[12];
    float*       out     = (float*)d_out;

    const int ZB = (N_NODES + 255) / 256;
    const int EB = (N_EDGES + 255) / 256;
    const int SB = (N_NODES + 1023) / 1024;

    detect_dtype<<<1, 1>>>(ei_w, batch_w);
    zero_cnt<<<ZB, 256>>>();
    hist_kernel<<<EB, 256>>>(ei_w);
    scan_block<<<SB, 1024>>>();
    scan_top<<<1, 64>>>(SB);
    scan_add<<<SB, 1024>>>();
    zero_cnt<<<ZB, 256>>>();
    scatter_kernel<<<EB, 256>>>(ei_w);

    dim3 gemm_grid(2, (N_NODES + 127) / 128);
    const int AGG_B = (N_NODES * 32 + 255) / 256;
    const int PREP128 = (32 * 8 * 32 + 255) / 256;
    const int PREP256 = (32 * 16 * 32 + 255) / 256;

    // ---- layer 0: x -> g_h -> g_fa ----
    prep_bfrag<<<PREP128, 256>>>(W0, NF);
    gemm_mma<<<gemm_grid, 256>>>(x, -1, NF);
    compute_al<<<N_NODES, 256>>>(as0, ad0);
    gat_aggregate<<<AGG_B, 256>>>(b0, 1);

    // ---- layer 1: g_fa -> g_h -> g_fb ----
    prep_bfrag<<<PREP256, 256>>>(Wh, HID);
    gemm_mma<<<gemm_grid, 256>>>(nullptr, 1, HID);
    compute_al<<<N_NODES, 256>>>(ash, adh);
    gat_aggregate<<<AGG_B, 256>>>(bh, 2);

    // ---- layer 2: g_fb -> g_h -> g_fa ----
    prep_bfrag<<<PREP256, 256>>>(Wh + HID * HID, HID);
    gemm_mma<<<gemm_grid, 256>>>(nullptr, 2, HID);
    compute_al<<<N_NODES, 256>>>(ash + HEADS * CH, adh + HEADS * CH);
    gat_aggregate<<<AGG_B, 256>>>(bh + HID, 1);

    // ---- pool + linear ----
    pool_linear<<<NG, 256>>>(batch_w, Wl, bl, out, 1);
}

// round 12
// speedup vs baseline: 1.0210x; 1.0210x over previous
#include <cuda_runtime.h>
#include <cuda_bf16.h>
#include <cuda_fp16.h>
#include <cstdint>

#define N_NODES 50000
#define N_EDGES 800000
#define NF      128
#define HID     256
#define HEADS   8
#define CH      32
#define NG      128
#define OUT_DIM 10
#define SLOPE   0.2f

// ---------------- scratch (device globals; no allocation) ----------------
__device__ float   g_h [(size_t)N_NODES * HID];
__device__ float   g_fa[(size_t)N_NODES * HID];
__device__ float   g_fb[(size_t)N_NODES * HID];
__device__ __half2 g_h16[(size_t)N_NODES * (HID / 2)];
__device__ float   g_als[N_NODES * HEADS];
__device__ float   g_ald[N_NODES * HEADS];
__device__ int     g_cnt[N_NODES];
__device__ int     g_rowptr[N_NODES + 1];
__device__ int     g_col[N_EDGES];
__device__ int     g_blk[128];
__device__ int     g_is64_edge;
__device__ int     g_is64_batch;
// B fragments (bf16 hi/lo, mma fragment order): [32 ntile][K/16 ks][32 lane][2 reg]
__device__ uint32_t g_bfrag_hi[32 * 16 * 32 * 2];
__device__ uint32_t g_bfrag_lo[32 * 16 * 32 * 2];

__device__ __forceinline__ float* buf_sel(int s) {
    return (s == 0) ? g_h : (s == 1) ? g_fa : g_fb;
}

__device__ __forceinline__ int ld_idx(const int* __restrict__ w, int i, int is64) {
    return is64 ? w[2 * i] : w[i];
}

// ---------------- dtype detection (int64 vs int32 index tensors) ----------------
__global__ void detect_dtype(const int* __restrict__ ei_w, const int* __restrict__ b_w) {
    int acc = 0;
    for (int i = 0; i < 512; i++) acc |= ei_w[2 * i + 1];
    g_is64_edge = (acc == 0) ? 1 : 0;
    int accb = 0;
    for (int i = N_NODES - 512; i < N_NODES; i += 2) accb |= b_w[i | 1];
    g_is64_batch = (accb == 0) ? 1 : 0;
}

// ---------------- CSR build kernels ----------------
__global__ void zero_cnt() {
    int i = blockIdx.x * blockDim.x + threadIdx.x;
    if (i < N_NODES) g_cnt[i] = 0;
}

__global__ void hist_kernel(const int* __restrict__ ei_w) {
    int e = blockIdx.x * blockDim.x + threadIdx.x;
    int is64 = g_is64_edge;
    if (e < N_EDGES) {
        int d = ld_idx(ei_w, N_EDGES + e, is64);
        atomicAdd(&g_cnt[d], 1);
    }
}

__global__ void scan_block() {
    __shared__ int s[1024];
    int tid = threadIdx.x;
    int i = blockIdx.x * 1024 + tid;
    int v = (i < N_NODES) ? g_cnt[i] : 0;
    s[tid] = v;
    __syncthreads();
    for (int off = 1; off < 1024; off <<= 1) {
        int a = (tid >= off) ? s[tid - off] : 0;
        __syncthreads();
        s[tid] += a;
        __syncthreads();
    }
    if (i < N_NODES) g_rowptr[i] = s[tid] - v;
    if (tid == 1023) g_blk[blockIdx.x] = s[1023];
}

__global__ void scan_top(int n) {
    __shared__ int s[64];
    int tid = threadIdx.x;
    int v = (tid < n) ? g_blk[tid] : 0;
    s[tid] = v;
    __syncthreads();
    for (int off = 1; off < 64; off <<= 1) {
        int a = (tid >= off) ? s[tid - off] : 0;
        __syncthreads();
        s[tid] += a;
        __syncthreads();
    }
    if (tid < n) g_blk[tid] = s[tid] - v;
}

__global__ void scan_add() {
    int i = blockIdx.x * 1024 + threadIdx.x;
    if (i < N_NODES) g_rowptr[i] += g_blk[i >> 10];
    if (i == 0) g_rowptr[N_NODES] = N_EDGES;
}

__global__ void scatter_kernel(const int* __restrict__ ei_w) {
    int e = blockIdx.x * blockDim.x + threadIdx.x;
    int is64 = g_is64_edge;
    if (e < N_EDGES) {
        int d = ld_idx(ei_w, N_EDGES + e, is64);
        int s = ld_idx(ei_w, e, is64);
        int pos = g_rowptr[d] + atomicAdd(&g_cnt[d], 1);
        g_col[pos] = s;
    }
}

// ---------------- bf16 split helpers ----------------
__device__ __forceinline__ void split_pack(float x0, float x1, uint32_t& hp, uint32_t& lp) {
    __nv_bfloat16 h0 = __float2bfloat16(x0);
    __nv_bfloat16 h1 = __float2bfloat16(x1);
    __nv_bfloat16 l0 = __float2bfloat16(x0 - __bfloat162float(h0));
    __nv_bfloat16 l1 = __float2bfloat16(x1 - __bfloat162float(h1));
    hp = ((uint32_t)__bfloat16_as_ushort(h1) << 16) | __bfloat16_as_ushort(h0);
    lp = ((uint32_t)__bfloat16_as_ushort(l1) << 16) | __bfloat16_as_ushort(l0);
}

__device__ __forceinline__ void mma_bf16(float* d, const uint32_t* a, uint32_t b0, uint32_t b1) {
    asm volatile(
        "mma.sync.aligned.m16n8k16.row.col.f32.bf16.bf16.f32 "
        "{%0,%1,%2,%3}, {%4,%5,%6,%7}, {%8,%9}, {%0,%1,%2,%3};"
        : "+f"(d[0]), "+f"(d[1]), "+f"(d[2]), "+f"(d[3])
        : "r"(a[0]), "r"(a[1]), "r"(a[2]), "r"(a[3]), "r"(b0), "r"(b1));
}

// ---------------- B fragment prep: W[K,256] -> hi/lo fragments ----------------
__global__ void prep_bfrag(const float* __restrict__ W, int K) {
    int idx = blockIdx.x * 256 + threadIdx.x;
    int nks = K >> 4;
    int total = 32 * nks * 32;
    if (idx >= total) return;
    int lane = idx & 31;
    int ks = (idx >> 5) % nks;
    int ntile = (idx >> 5) / nks;
    int n = ntile * 8 + (lane >> 2);
    int kb = ks * 16 + (lane & 3) * 2;
    uint32_t h0, l0, h1, l1;
    split_pack(W[(size_t)kb * 256 + n],       W[(size_t)(kb + 1) * 256 + n], h0, l0);
    split_pack(W[(size_t)(kb + 8) * 256 + n], W[(size_t)(kb + 9) * 256 + n], h1, l1);
    g_bfrag_hi[idx * 2 + 0] = h0;
    g_bfrag_hi[idx * 2 + 1] = h1;
    g_bfrag_lo[idx * 2 + 0] = l0;
    g_bfrag_lo[idx * 2 + 1] = l1;
}

// ---------------- split-bf16 mma.sync GEMM: g_h[M,256] = A[M,K] @ W[K,256] ----------------
__global__ __launch_bounds__(256) void gemm_mma(const float* __restrict__ Aext,
                                                int a_sel, int K) {
    __shared__ uint32_t sAhi[8 * 4 * 32 * 4];   // 16KB
    __shared__ uint32_t sAlo[8 * 4 * 32 * 4];   // 16KB

    const float* A = (a_sel < 0) ? Aext : buf_sel(a_sel);
    float* C = g_h;
    const int nks = K >> 4;

    int tid = threadIdx.x;
    int lane = tid & 31, wid = tid >> 5;
    int wm = wid & 3, wn = wid >> 2;
    int grp = lane >> 2, tig = lane & 3;
    int bm = blockIdx.y, bn = blockIdx.x;

    int arow = tid >> 1;
    int akb  = (tid & 1) * 32;
    int grow = bm * 128 + arow;
    bool avalid = (grow < N_NODES);
    int amt = arow >> 4, ar8 = (arow >> 3) & 1, agrp = arow & 7;

    float acc[2][8][4];
#pragma unroll
    for (int mt = 0; mt < 2; mt++)
#pragma unroll
        for (int nt = 0; nt < 8; nt++)
#pragma unroll
            for (int r = 0; r < 4; r++) acc[mt][nt][r] = 0.0f;

    const int niter = K >> 6;
    float4 av[8];
    // preload iter 0
#pragma unroll
    for (int jj = 0; jj < 8; jj++)
        av[jj] = avalid ? *(const float4*)(A + (size_t)grow * K + akb + jj * 4)
                        : make_float4(0.f, 0.f, 0.f, 0.f);

    for (int it = 0; it < niter; it++) {
        // ---- convert current registers -> smem fragment order ----
#pragma unroll
        for (int jj = 0; jj < 8; jj++) {
            float4 v = av[jj];
#pragma unroll
            for (int q = 0; q < 2; q++) {
                uint32_t hp, lp;
                split_pack(q ? v.z : v.x, q ? v.w : v.y, hp, lp);
                int kq = akb + jj * 4 + 2 * q;
                int ks = kq >> 4;
                int kk = kq & 15;
                int reg = (kk >> 3) * 2 + ar8;
                int lt = agrp * 4 + ((kk & 7) >> 1);
                int addr = ((amt * 4 + ks) * 32 + lt) * 4 + reg;
                sAhi[addr] = hp;
                sAlo[addr] = lp;
            }
        }
        __syncthreads();

        // ---- prefetch next iter's A while MMAs run ----
        if (it + 1 < niter) {
            const float* Ap = A + (size_t)grow * K + (it + 1) * 64 + akb;
#pragma unroll
            for (int jj = 0; jj < 8; jj++)
                av[jj] = avalid ? *(const float4*)(Ap + jj * 4)
                                : make_float4(0.f, 0.f, 0.f, 0.f);
        }

        // ---- consume: 4 k16-steps ----
#pragma unroll
        for (int ks = 0; ks < 4; ks++) {
            int ksg = it * 4 + ks;
            uint32_t ah[2][4], al[2][4];
#pragma unroll
            for (int mt = 0; mt < 2; mt++) {
                int mtg = wm * 2 + mt;
                int base = ((mtg * 4 + ks) * 32 + lane) * 4;
                *(uint4*)ah[mt] = *(const uint4*)&sAhi[base];
                *(uint4*)al[mt] = *(const uint4*)&sAlo[base];
            }
#pragma unroll
            for (int nt = 0; nt < 8; nt++) {
                int ntg = bn * 16 + wn * 8 + nt;
                int boff = ((ntg * nks + ksg) * 32 + lane);
                uint2 bh = *((const uint2*)g_bfrag_hi + boff);
                uint2 bl = *((const uint2*)g_bfrag_lo + boff);
#pragma unroll
                for (int mt = 0; mt < 2; mt++) {
                    mma_bf16(acc[mt][nt], ah[mt], bl.x, bl.y);
                    mma_bf16(acc[mt][nt], al[mt], bh.x, bh.y);
                    mma_bf16(acc[mt][nt], ah[mt], bh.x, bh.y);
                }
            }
        }
        __syncthreads();
    }

    // ---- epilogue ----
#pragma unroll
    for (int mt = 0; mt < 2; mt++) {
        int r0 = bm * 128 + wm * 32 + mt * 16 + grp;
#pragma unroll
        for (int nt = 0; nt < 8; nt++) {
            int cc = bn * 128 + wn * 64 + nt * 8 + tig * 2;
            if (r0 < N_NODES)
                *(float2*)(C + (size_t)r0 * 256 + cc) = make_float2(acc[mt][nt][0], acc[mt][nt][1]);
            if (r0 + 8 < N_NODES)
                *(float2*)(C + (size_t)(r0 + 8) * 256 + cc) = make_float2(acc[mt][nt][2], acc[mt][nt][3]);
        }
    }
}

// ---------------- attention logits + fp16 pack ----------------
__global__ __launch_bounds__(256) void compute_al(const float* __restrict__ a_src,
                                                  const float* __restrict__ a_dst) {
    int v = blockIdx.x;
    int t = threadIdx.x;
    int w = t >> 5;
    int lane = t & 31;
    float hv = g_h[(size_t)v * HID + t];

    // pack fp16 copy: even thread packs (hv, next thread's hv)
    float partner = __shfl_xor_sync(0xffffffffu, hv, 1);
    if ((t & 1) == 0)
        g_h16[(size_t)v * (HID / 2) + (t >> 1)] = __floats2half2_rn(hv, partner);

    float s1 = hv * a_src[t];
    float s2 = hv * a_dst[t];
#pragma unroll
    for (int off = 16; off; off >>= 1) {
        s1 += __shfl_xor_sync(0xffffffffu, s1, off);
        s2 += __shfl_xor_sync(0xffffffffu, s2, off);
    }
    if (lane == 0) {
        g_als[v * HEADS + w] = s1;
        g_ald[v * HEADS + w] = s2;
    }
}

// ---------------- warp-per-node softmax attention aggregation (fp16 gathers) ----------------
// lane owns channels [lane*8, lane*8+8) -> head = lane>>2 (static). No local-mem arrays.
__global__ __launch_bounds__(256) void gat_aggregate(const float* __restrict__ bias,
                                                     int out_sel) {
    float* out = buf_sel(out_sel);
    int warp = (blockIdx.x * blockDim.x + threadIdx.x) >> 5;
    int lane = threadIdx.x & 31;
    if (warp >= N_NODES) return;
    int v = warp;
    int r0 = g_rowptr[v];
    int deg = g_rowptr[v + 1] - r0;
    int hd = lane >> 2;

    // ---- pass 1: per-head max of als over in-neighbors (+ self) ----
    const float4* als4 = (const float4*)g_als;
    float4 M0 = make_float4(-1e30f, -1e30f, -1e30f, -1e30f);
    float4 M1 = M0;
    for (int i = lane; i < deg + 1; i += 32) {
        int s = (i < deg) ? g_col[r0 + i] : v;
        float4 a0 = als4[s * 2], a1 = als4[s * 2 + 1];
        M0.x = fmaxf(M0.x, a0.x); M0.y = fmaxf(M0.y, a0.y);
        M0.z = fmaxf(M0.z, a0.z); M0.w = fmaxf(M0.w, a0.w);
        M1.x = fmaxf(M1.x, a1.x); M1.y = fmaxf(M1.y, a1.y);
        M1.z = fmaxf(M1.z, a1.z); M1.w = fmaxf(M1.w, a1.w);
    }
    float Mx[8] = {M0.x, M0.y, M0.z, M0.w, M1.x, M1.y, M1.z, M1.w};
#pragma unroll
    for (int k = 0; k < 8; k++)
#pragma unroll
        for (int off = 16; off; off >>= 1)
            Mx[k] = fmaxf(Mx[k], __shfl_xor_sync(0xffffffffu, Mx[k], off));

    float4 ad0 = als4[(N_NODES + v) * 2 - N_NODES * 2 + 0];  // placeholder avoided below
    // load ald directly
    const float4* ald4 = (const float4*)g_ald;
    float4 d0 = ald4[v * 2], d1 = ald4[v * 2 + 1];
    float aldv[8] = {d0.x, d0.y, d0.z, d0.w, d1.x, d1.y, d1.z, d1.w};

    // m per head: leaky(Mx + ald) (leaky_relu is monotonic)
    float mh[8];
#pragma unroll
    for (int k = 0; k < 8; k++) {
        float e = Mx[k] + aldv[k];
        mh[k] = (e > 0.f) ? e : SLOPE * e;
    }
    // ladder-select this lane's head values (static unroll, no local mem)
    float mhd = mh[0], aldhd = aldv[0];
#pragma unroll
    for (int k = 1; k < 8; k++) {
        bool p = (hd == k);
        mhd   = p ? mh[k]   : mhd;
        aldhd = p ? aldv[k] : aldhd;
    }

    // ---- pass 2: fused exp-sum + weighted accumulation ----
    float acc[8];
#pragma unroll
    for (int j = 0; j < 8; j++) acc[j] = 0.0f;
    float den = 0.0f;
    const __half2* h2base = g_h16;
    for (int i = 0; i <= deg; i++) {
        int s = (i < deg) ? g_col[r0 + i] : v;
        float e = g_als[s * HEADS + hd] + aldhd;
        e = (e > 0.f) ? e : SLOPE * e;
        float ex = __expf(e - mhd);
        den += ex;
        const __half2* row = h2base + (size_t)s * (HID / 2) + lane * 4;
#pragma unroll
        for (int j = 0; j < 4; j++) {
            float2 f = __half22float2(row[j]);
            acc[2 * j]     = fmaf(ex, f.x, acc[2 * j]);
            acc[2 * j + 1] = fmaf(ex, f.y, acc[2 * j + 1]);
        }
    }
    float inv = 1.0f / (den + 1e-16f);
    float* op = out + (size_t)v * HID + lane * 8;
    const float* bp = bias + lane * 8;
    float4 o0 = make_float4(acc[0] * inv + bp[0], acc[1] * inv + bp[1],
                            acc[2] * inv + bp[2], acc[3] * inv + bp[3]);
    float4 o1 = make_float4(acc[4] * inv + bp[4], acc[5] * inv + bp[5],
                            acc[6] * inv + bp[6], acc[7] * inv + bp[7]);
    *(float4*)(op + 0) = o0;
    *(float4*)(op + 4) = o1;
}

// ---------------- mean pool (sorted batch) + final linear, fused ----------------
__device__ __forceinline__ int lower_bound_idx(const int* __restrict__ w, int key, int is64) {
    int lo = 0, hi = N_NODES;
    while (lo < hi) {
        int mid = (lo + hi) >> 1;
        if (ld_idx(w, mid, is64) < key) lo = mid + 1; else hi = mid;
    }
    return lo;
}

__global__ __launch_bounds__(256) void pool_linear(const int* __restrict__ batch_w,
                                                   const float* __restrict__ Wl,
                                                   const float* __restrict__ bl,
                                                   float* __restrict__ out,
                                                   int feat_sel) {
    const float* feat = buf_sel(feat_sel);
    int is64 = g_is64_batch;
    int g = blockIdx.x;
    int tid = threadIdx.x;
    int start = lower_bound_idx(batch_w, g, is64);
    int end   = lower_bound_idx(batch_w, g + 1, is64);
    float acc = 0.0f;
    for (int n = start; n < end; n++) acc += feat[(size_t)n * HID + tid];
    int cnt = end - start;
    float pooled = acc / fmaxf((float)cnt, 1.0f);
    __shared__ float spool[HID];
    spool[tid] = pooled;
    __syncthreads();
    if (tid < OUT_DIM) {
        float o = bl[tid];
        for (int c = 0; c < HID; c++) o = fmaf(spool[c], Wl[c * OUT_DIM + tid], o);
        out[g * OUT_DIM + tid] = o;
    }
}

// ---------------- host launch ----------------
extern "C" void kernel_launch(void* const* d_in, const int* in_sizes, int n_in,
                              void* d_out, int out_size) {
    const float* x       = (const float*)d_in[0];
    const int*   ei_w    = (const int*)d_in[1];
    const int*   batch_w = (const int*)d_in[2];
    const float* W0      = (const float*)d_in[3];
    const float* as0     = (const float*)d_in[4];
    const float* ad0     = (const float*)d_in[5];
    const float* b0      = (const float*)d_in[6];
    const float* Wh      = (const float*)d_in[7];
    const float* ash     = (const float*)d_in[8];
    const float* adh     = (const float*)d_in[9];
    const float* bh      = (const float*)d_in[10];
    const float* Wl      = (const float*)d_in[11];
    const float* bl      = (const float*)d_in[12];
    float*       out     = (float*)d_out;

    const int ZB = (N_NODES + 255) / 256;
    const int EB = (N_EDGES + 255) / 256;
    const int SB = (N_NODES + 1023) / 1024;

    detect_dtype<<<1, 1>>>(ei_w, batch_w);
    zero_cnt<<<ZB, 256>>>();
    hist_kernel<<<EB, 256>>>(ei_w);
    scan_block<<<SB, 1024>>>();
    scan_top<<<1, 64>>>(SB);
    scan_add<<<SB, 1024>>>();
    zero_cnt<<<ZB, 256>>>();
    scatter_kernel<<<EB, 256>>>(ei_w);

    dim3 gemm_grid(2, (N_NODES + 127) / 128);
    const int AGG_B = (N_NODES * 32 + 255) / 256;
    const int PREP128 = (32 * 8 * 32 + 255) / 256;
    const int PREP256 = (32 * 16 * 32 + 255) / 256;

    // ---- layer 0: x -> g_h -> g_fa ----
    prep_bfrag<<<PREP128, 256>>>(W0, NF);
    gemm_mma<<<gemm_grid, 256>>>(x, -1, NF);
    compute_al<<<N_NODES, 256>>>(as0, ad0);
    gat_aggregate<<<AGG_B, 256>>>(b0, 1);

    // ---- layer 1: g_fa -> g_h -> g_fb ----
    prep_bfrag<<<PREP256, 256>>>(Wh, HID);
    gemm_mma<<<gemm_grid, 256>>>(nullptr, 1, HID);
    compute_al<<<N_NODES, 256>>>(ash, adh);
    gat_aggregate<<<AGG_B, 256>>>(bh, 2);

    // ---- layer 2: g_fb -> g_h -> g_fa ----
    prep_bfrag<<<PREP256, 256>>>(Wh + HID * HID, HID);
    gemm_mma<<<gemm_grid, 256>>>(nullptr, 2, HID);
    compute_al<<<N_NODES, 256>>>(ash + HEADS * CH, adh + HEADS * CH);
    gat_aggregate<<<AGG_B, 256>>>(bh + HID, 1);

    // ---- pool + linear ----
    pool_linear<<<NG, 256>>>(batch_w, Wl, bl, out, 1);
}